// round 9
// baseline (speedup 1.0000x reference)
#include <cuda_runtime.h>

#define NN 100000
#define NE 1600000
#define SCAN_B 1024
#define SCAN_NB ((NN + SCAN_B - 1) / SCAN_B)   // 98

// Scratch (static device globals — no dynamic allocation allowed)
__device__ float4 g_zs[NN * 16];    // z * dinv   [N,64]
__device__ float4 g_agg1[NN * 16];  // layer-1 aggregation result [N,64]
__device__ float4 g_x1[NN * 32];    // relu(gcn1) [N,128]
__device__ float4 g_hs2[NN * 16];   // (x1@W2)*dinv [N,64]
__device__ float  g_dinv[NN];
__device__ int    g_cnt[NN];        // in-degree (edges only)
__device__ int    g_off[NN];        // CSR row offsets (exclusive prefix of cnt)
__device__ int    g_cur[NN];        // mutable cursor for permute
__device__ int    g_esrc[NE];       // src indices sorted by dst
__device__ int    g_bsum[128];      // scan block sums
__device__ int    g_layout;         // 1 = int64 pairs, 0 = int32

// Fused: zero g_cnt + detect edge_index storage (block 0 does detection).
__global__ void k_init(const int* __restrict__ ei) {
    int i = blockIdx.x * 256 + threadIdx.x;
    if (i < NN) g_cnt[i] = 0;
    if (blockIdx.x == 0) {
        __shared__ int nz;
        if (threadIdx.x == 0) nz = 0;
        __syncthreads();
        if (ei[2 * threadIdx.x + 1] != 0) atomicOr(&nz, 1);
        __syncthreads();
        if (threadIdx.x == 0) g_layout = (nz == 0) ? 1 : 0;
    }
}

__device__ __forceinline__ int edge_src(const int* __restrict__ ei, int e, int layout) {
    return layout ? ei[2 * e] : ei[e];
}
__device__ __forceinline__ int edge_dst(const int* __restrict__ ei, int e, int layout) {
    return layout ? ei[2 * (NE + e)] : ei[NE + e];
}

// Histogram of destinations, 4 edges/thread via int4 (int32 path)
__global__ void k_hist(const int* __restrict__ ei) {
    int t = blockIdx.x * 256 + threadIdx.x;
    int e = t * 4;
    if (e >= NE) return;
    if (g_layout == 0) {
        int4 d4 = __ldg((const int4*)(ei + NE) + t);
        if ((unsigned)d4.x < NN) atomicAdd(&g_cnt[d4.x], 1);
        if ((unsigned)d4.y < NN) atomicAdd(&g_cnt[d4.y], 1);
        if ((unsigned)d4.z < NN) atomicAdd(&g_cnt[d4.z], 1);
        if ((unsigned)d4.w < NN) atomicAdd(&g_cnt[d4.w], 1);
    } else {
#pragma unroll
        for (int q = 0; q < 4; ++q) {
            int d = edge_dst(ei, e + q, 1);
            if ((unsigned)d < NN) atomicAdd(&g_cnt[d], 1);
        }
    }
}

// Block-level exclusive scan (Hillis-Steele), emits per-block totals.
__global__ void k_scan1() {
    __shared__ int sh[SCAN_B];
    int i = blockIdx.x * SCAN_B + threadIdx.x;
    int v = (i < NN) ? g_cnt[i] : 0;
    sh[threadIdx.x] = v;
    __syncthreads();
#pragma unroll
    for (int ofs = 1; ofs < SCAN_B; ofs <<= 1) {
        int t = (threadIdx.x >= ofs) ? sh[threadIdx.x - ofs] : 0;
        __syncthreads();
        sh[threadIdx.x] += t;
        __syncthreads();
    }
    if (i < NN) g_off[i] = sh[threadIdx.x] - v;   // exclusive
    if (threadIdx.x == SCAN_B - 1) g_bsum[blockIdx.x] = sh[SCAN_B - 1];
}

// Scan the block sums (single block, 128 >= SCAN_NB)
__global__ void k_scan2() {
    __shared__ int sh[128];
    int v = (threadIdx.x < SCAN_NB) ? g_bsum[threadIdx.x] : 0;
    sh[threadIdx.x] = v;
    __syncthreads();
#pragma unroll
    for (int ofs = 1; ofs < 128; ofs <<= 1) {
        int t = (threadIdx.x >= ofs) ? sh[threadIdx.x - ofs] : 0;
        __syncthreads();
        sh[threadIdx.x] += t;
        __syncthreads();
    }
    g_bsum[threadIdx.x] = sh[threadIdx.x] - v;    // exclusive
}

// Fused scan3 + scale_init: NN*16 threads, one float4 column per thread.
// All threads compute dinv in-register; lane f==0 finalizes offsets.
__global__ void k_prep(const float4* __restrict__ z4) {
    int u = blockIdx.x * 256 + threadIdx.x;  // exactly NN*16
    int node = u >> 4;
    int f = u & 15;
    float dinv = rsqrtf((float)g_cnt[node] + 1.0f);
    if (f == 0) {
        int o = g_off[node] + g_bsum[node >> 10];
        g_off[node] = o;
        g_cur[node] = o;
        g_dinv[node] = dinv;
    }
    float4 v = __ldg(z4 + u);
    v.x *= dinv; v.y *= dinv; v.z *= dinv; v.w *= dinv;
    g_zs[u] = v;
}

// Counting-sort edges by destination, 4 edges/thread via int4 (int32 path)
__global__ void k_permute(const int* __restrict__ ei) {
    int t = blockIdx.x * 256 + threadIdx.x;
    int e = t * 4;
    if (e >= NE) return;
    if (g_layout == 0) {
        int4 s4 = __ldg((const int4*)ei + t);
        int4 d4 = __ldg((const int4*)(ei + NE) + t);
        if ((unsigned)s4.x < NN && (unsigned)d4.x < NN) g_esrc[atomicAdd(&g_cur[d4.x], 1)] = s4.x;
        if ((unsigned)s4.y < NN && (unsigned)d4.y < NN) g_esrc[atomicAdd(&g_cur[d4.y], 1)] = s4.y;
        if ((unsigned)s4.z < NN && (unsigned)d4.z < NN) g_esrc[atomicAdd(&g_cur[d4.z], 1)] = s4.z;
        if ((unsigned)s4.w < NN && (unsigned)d4.w < NN) g_esrc[atomicAdd(&g_cur[d4.w], 1)] = s4.w;
    } else {
#pragma unroll
        for (int q = 0; q < 4; ++q) {
            int s = edge_src(ei, e + q, 1);
            int d = edge_dst(ei, e + q, 1);
            if ((unsigned)s < NN && (unsigned)d < NN)
                g_esrc[atomicAdd(&g_cur[d], 1)] = s;
        }
    }
}

// Gather-side segment sum: ONE WARP per node. Lane f = lane&15 owns one
// float4 column; halves (lane>>4) process even/odd edges. Final shfl combine.
// FIRST: in = g_zs, out = g_agg1 (self-loop seeded).
// else : in = g_hs2, out = d_out with fused (*dinv[dst] + b2) epilogue.
template <bool FIRST>
__global__ void k_gather(float4* __restrict__ dout, const float4* __restrict__ b2v) {
    int gw = (blockIdx.x * 256 + threadIdx.x) >> 5;  // global warp = node
    int lane = threadIdx.x & 31;
    int node = gw;                                    // grid sized so gw < NN
    int f = lane & 15;
    int half = lane >> 4;
    const float4* hs = FIRST ? (const float4*)g_zs : (const float4*)g_hs2;

    float4 acc = make_float4(0.f, 0.f, 0.f, 0.f);
    if (half == 0) acc = __ldg(hs + (size_t)node * 16 + f);  // self-loop seed

    int off = g_off[node];
    int end = off + g_cnt[node];
    int j = off + half;
    // 4 edges per half per iteration => 8 outstanding payload loads per warp
    for (; j + 6 < end; j += 8) {
        int s0 = __ldg(&g_esrc[j]);
        int s1 = __ldg(&g_esrc[j + 2]);
        int s2 = __ldg(&g_esrc[j + 4]);
        int s3 = __ldg(&g_esrc[j + 6]);
        float4 v0 = __ldg(hs + (size_t)s0 * 16 + f);
        float4 v1 = __ldg(hs + (size_t)s1 * 16 + f);
        float4 v2 = __ldg(hs + (size_t)s2 * 16 + f);
        float4 v3 = __ldg(hs + (size_t)s3 * 16 + f);
        acc.x += (v0.x + v1.x) + (v2.x + v3.x);
        acc.y += (v0.y + v1.y) + (v2.y + v3.y);
        acc.z += (v0.z + v1.z) + (v2.z + v3.z);
        acc.w += (v0.w + v1.w) + (v2.w + v3.w);
    }
    for (; j < end; j += 2) {
        int s0 = __ldg(&g_esrc[j]);
        float4 v0 = __ldg(hs + (size_t)s0 * 16 + f);
        acc.x += v0.x; acc.y += v0.y; acc.z += v0.z; acc.w += v0.w;
    }
    // combine odd half into even half
    acc.x += __shfl_down_sync(0xffffffffu, acc.x, 16);
    acc.y += __shfl_down_sync(0xffffffffu, acc.y, 16);
    acc.z += __shfl_down_sync(0xffffffffu, acc.z, 16);
    acc.w += __shfl_down_sync(0xffffffffu, acc.w, 16);

    if (half == 0) {
        if (FIRST) {
            g_agg1[(size_t)node * 16 + f] = acc;
        } else {
            float sc = g_dinv[node];
            float4 b = __ldg(b2v + f);
            acc.x = acc.x * sc + b.x; acc.y = acc.y * sc + b.y;
            acc.z = acc.z * sc + b.z; acc.w = acc.w * sc + b.w;
            dout[(size_t)node * 16 + f] = acc;
        }
    }
}

// Dense GEMM: ROWS rows/block, 256 threads, R=4 rows/thread, float4 zk loads.
// EPI==1: in = g_agg1 (rows scaled by dinv at load), out = relu(acc + b1) -> g_x1
// EPI==2: in = g_x1,  out = acc * dinv[row] -> g_hs2   (pre-scale by dinv[src])
template <int K, int N, int ROWS, int EPI>
__global__ void __launch_bounds__(256) k_gemm(const float* __restrict__ W,
                                              const float* __restrict__ bias) {
    constexpr int TPR = N / 8;          // threads per row-group (8 outputs each)
    constexpr int GROUPS = 256 / TPR;   // row groups per block
    constexpr int R = ROWS / GROUPS;    // rows per thread (4)
    constexpr int KT = 32;
    constexpr int RST = KT + 4;         // float stride, keeps float4 alignment

    __shared__ __align__(16) float Ws[KT * N];
    __shared__ __align__(16) float Rs[ROWS * RST];

    const float* in = (EPI == 1) ? (const float*)g_agg1 : (const float*)g_x1;

    int tid = threadIdx.x;
    int c = tid % TPR;
    int g = tid / TPR;
    int row0 = blockIdx.x * ROWS;

    float4 a0[R], a1[R];
#pragma unroll
    for (int i = 0; i < R; i++) {
        a0[i] = make_float4(0.f, 0.f, 0.f, 0.f);
        a1[i] = make_float4(0.f, 0.f, 0.f, 0.f);
    }

#pragma unroll
    for (int kt = 0; kt < K / KT; ++kt) {
        const float4* Wg = (const float4*)(W + kt * KT * N);
        float4* Ws4 = (float4*)Ws;
#pragma unroll
        for (int j = tid; j < KT * N / 4; j += 256) Ws4[j] = __ldg(Wg + j);
#pragma unroll
        for (int j = tid; j < ROWS * (KT / 4); j += 256) {
            int r = j / (KT / 4), c4 = j % (KT / 4);
            int grow = row0 + r;
            if (grow >= NN) grow = NN - 1;
            float4 v = __ldg((const float4*)(in + (size_t)grow * K + kt * KT) + c4);
            if (EPI == 1) {
                float sc = g_dinv[grow];
                v.x *= sc; v.y *= sc; v.z *= sc; v.w *= sc;
            }
            *(float4*)&Rs[r * RST + c4 * 4] = v;
        }
        __syncthreads();

        const float4* Wr = (const float4*)Ws;
#pragma unroll
        for (int kk4 = 0; kk4 < KT / 4; ++kk4) {
            float4 zk[R];
#pragma unroll
            for (int i = 0; i < R; ++i)
                zk[i] = *(const float4*)&Rs[(g * R + i) * RST + kk4 * 4];
#pragma unroll
            for (int kc = 0; kc < 4; ++kc) {
                float4 w0 = Wr[(kk4 * 4 + kc) * (N / 4) + 2 * c];
                float4 w1 = Wr[(kk4 * 4 + kc) * (N / 4) + 2 * c + 1];
#pragma unroll
                for (int i = 0; i < R; ++i) {
                    float z = (kc == 0) ? zk[i].x : (kc == 1) ? zk[i].y
                             : (kc == 2) ? zk[i].z : zk[i].w;
                    a0[i].x += z * w0.x; a0[i].y += z * w0.y;
                    a0[i].z += z * w0.z; a0[i].w += z * w0.w;
                    a1[i].x += z * w1.x; a1[i].y += z * w1.y;
                    a1[i].z += z * w1.z; a1[i].w += z * w1.w;
                }
            }
        }
        __syncthreads();
    }

#pragma unroll
    for (int i = 0; i < R; ++i) {
        int grow = row0 + g * R + i;
        if (grow >= NN) continue;
        if (EPI == 1) {
            float4 bb0 = __ldg((const float4*)bias + 2 * c);
            float4 bb1 = __ldg((const float4*)bias + 2 * c + 1);
            float4 v0, v1;
            v0.x = fmaxf(a0[i].x + bb0.x, 0.f); v0.y = fmaxf(a0[i].y + bb0.y, 0.f);
            v0.z = fmaxf(a0[i].z + bb0.z, 0.f); v0.w = fmaxf(a0[i].w + bb0.w, 0.f);
            v1.x = fmaxf(a1[i].x + bb1.x, 0.f); v1.y = fmaxf(a1[i].y + bb1.y, 0.f);
            v1.z = fmaxf(a1[i].z + bb1.z, 0.f); v1.w = fmaxf(a1[i].w + bb1.w, 0.f);
            float4* op = (float4*)g_x1 + (size_t)grow * (N / 4);
            op[2 * c] = v0;
            op[2 * c + 1] = v1;
        } else {
            float sc = g_dinv[grow];
            float4 v0, v1;
            v0.x = a0[i].x * sc; v0.y = a0[i].y * sc; v0.z = a0[i].z * sc; v0.w = a0[i].w * sc;
            v1.x = a1[i].x * sc; v1.y = a1[i].y * sc; v1.z = a1[i].z * sc; v1.w = a1[i].w * sc;
            float4* h = (float4*)g_hs2 + (size_t)grow * (N / 4);
            h[2 * c] = v0;
            h[2 * c + 1] = v1;
        }
    }
}

extern "C" void kernel_launch(void* const* d_in, const int* in_sizes, int n_in,
                              void* d_out, int out_size) {
    const float* z   = (const float*)d_in[0];
    const int* ei    = (const int*)d_in[1];   // int32 OR int64 pairs (detected)
    const float* W1  = (const float*)d_in[2];
    const float* b1  = (const float*)d_in[3];
    const float* W2  = (const float*)d_in[4];
    const float* b2  = (const float*)d_in[5];
    float* out = (float*)d_out;

    k_init<<<(NN + 255) / 256, 256>>>(ei);
    k_hist<<<(NE / 4 + 255) / 256, 256>>>(ei);
    k_scan1<<<SCAN_NB, SCAN_B>>>();
    k_scan2<<<1, 128>>>();
    k_prep<<<NN * 16 / 256, 256>>>((const float4*)z);
    k_permute<<<(NE / 4 + 255) / 256, 256>>>(ei);
    k_gather<true><<<NN * 32 / 256, 256>>>(nullptr, nullptr);
    k_gemm<64, 128, 64, 1><<<(NN + 63) / 64, 256>>>(W1, b1);
    k_gemm<128, 64, 128, 2><<<(NN + 127) / 128, 256>>>(W2, nullptr);
    k_gather<false><<<NN * 32 / 256, 256>>>((float4*)out, (const float4*)b2);
}

// round 10
// speedup vs baseline: 1.0704x; 1.0704x over previous
#include <cuda_runtime.h>

#define NN 100000
#define NE 1600000
#define SCAN_B 1024
#define SCAN_NB ((NN + SCAN_B - 1) / SCAN_B)   // 98

// Scratch (static device globals — no dynamic allocation allowed)
__device__ float4 g_zs[NN * 16];    // z * dinv   [N,64]
__device__ float4 g_agg1[NN * 16];  // layer-1 aggregation result [N,64]
__device__ float4 g_x1[NN * 32];    // relu(gcn1) [N,128]
__device__ float4 g_hs2[NN * 16];   // (x1@W2)*dinv [N,64]
__device__ float  g_dinv[NN];
__device__ int    g_cnt[NN];        // in-degree (edges only)
__device__ int    g_off[NN];        // CSR row offsets (exclusive prefix of cnt)
__device__ int    g_cur[NN];        // mutable cursor for permute
__device__ int    g_esrc[NE];       // src indices sorted by dst
__device__ int    g_bsum[128];      // scan block sums
__device__ int    g_layout;         // 1 = int64 pairs, 0 = int32

// Fused: zero g_cnt + detect edge_index storage (block 0 does detection).
__global__ void k_init(const int* __restrict__ ei) {
    int i = blockIdx.x * 256 + threadIdx.x;
    if (i < NN) g_cnt[i] = 0;
    if (blockIdx.x == 0) {
        __shared__ int nz;
        if (threadIdx.x == 0) nz = 0;
        __syncthreads();
        if (ei[2 * threadIdx.x + 1] != 0) atomicOr(&nz, 1);
        __syncthreads();
        if (threadIdx.x == 0) g_layout = (nz == 0) ? 1 : 0;
    }
}

__device__ __forceinline__ int edge_src(const int* __restrict__ ei, int e, int layout) {
    return layout ? ei[2 * e] : ei[e];
}
__device__ __forceinline__ int edge_dst(const int* __restrict__ ei, int e, int layout) {
    return layout ? ei[2 * (NE + e)] : ei[NE + e];
}

// Histogram of destinations, 4 edges/thread via int4 (int32 path)
__global__ void k_hist(const int* __restrict__ ei) {
    int t = blockIdx.x * 256 + threadIdx.x;
    int e = t * 4;
    if (e >= NE) return;
    if (g_layout == 0) {
        int4 d4 = __ldg((const int4*)(ei + NE) + t);
        if ((unsigned)d4.x < NN) atomicAdd(&g_cnt[d4.x], 1);
        if ((unsigned)d4.y < NN) atomicAdd(&g_cnt[d4.y], 1);
        if ((unsigned)d4.z < NN) atomicAdd(&g_cnt[d4.z], 1);
        if ((unsigned)d4.w < NN) atomicAdd(&g_cnt[d4.w], 1);
    } else {
#pragma unroll
        for (int q = 0; q < 4; ++q) {
            int d = edge_dst(ei, e + q, 1);
            if ((unsigned)d < NN) atomicAdd(&g_cnt[d], 1);
        }
    }
}

// Block-level exclusive scan (Hillis-Steele), emits per-block totals.
__global__ void k_scan1() {
    __shared__ int sh[SCAN_B];
    int i = blockIdx.x * SCAN_B + threadIdx.x;
    int v = (i < NN) ? g_cnt[i] : 0;
    sh[threadIdx.x] = v;
    __syncthreads();
#pragma unroll
    for (int ofs = 1; ofs < SCAN_B; ofs <<= 1) {
        int t = (threadIdx.x >= ofs) ? sh[threadIdx.x - ofs] : 0;
        __syncthreads();
        sh[threadIdx.x] += t;
        __syncthreads();
    }
    if (i < NN) g_off[i] = sh[threadIdx.x] - v;   // exclusive
    if (threadIdx.x == SCAN_B - 1) g_bsum[blockIdx.x] = sh[SCAN_B - 1];
}

// Scan the block sums (single block, 128 >= SCAN_NB)
__global__ void k_scan2() {
    __shared__ int sh[128];
    int v = (threadIdx.x < SCAN_NB) ? g_bsum[threadIdx.x] : 0;
    sh[threadIdx.x] = v;
    __syncthreads();
#pragma unroll
    for (int ofs = 1; ofs < 128; ofs <<= 1) {
        int t = (threadIdx.x >= ofs) ? sh[threadIdx.x - ofs] : 0;
        __syncthreads();
        sh[threadIdx.x] += t;
        __syncthreads();
    }
    g_bsum[threadIdx.x] = sh[threadIdx.x] - v;    // exclusive
}

// Fused scan3 + scale_init: NN*16 threads, one float4 column per thread.
// All threads compute dinv in-register; lane f==0 finalizes offsets.
__global__ void k_prep(const float4* __restrict__ z4) {
    int u = blockIdx.x * 256 + threadIdx.x;  // exactly NN*16
    int node = u >> 4;
    int f = u & 15;
    float dinv = rsqrtf((float)g_cnt[node] + 1.0f);
    if (f == 0) {
        int o = g_off[node] + g_bsum[node >> 10];
        g_off[node] = o;
        g_cur[node] = o;
        g_dinv[node] = dinv;
    }
    float4 v = __ldg(z4 + u);
    v.x *= dinv; v.y *= dinv; v.z *= dinv; v.w *= dinv;
    g_zs[u] = v;
}

// Counting-sort edges by destination, 4 edges/thread via int4 (int32 path)
__global__ void k_permute(const int* __restrict__ ei) {
    int t = blockIdx.x * 256 + threadIdx.x;
    int e = t * 4;
    if (e >= NE) return;
    if (g_layout == 0) {
        int4 s4 = __ldg((const int4*)ei + t);
        int4 d4 = __ldg((const int4*)(ei + NE) + t);
        if ((unsigned)s4.x < NN && (unsigned)d4.x < NN) g_esrc[atomicAdd(&g_cur[d4.x], 1)] = s4.x;
        if ((unsigned)s4.y < NN && (unsigned)d4.y < NN) g_esrc[atomicAdd(&g_cur[d4.y], 1)] = s4.y;
        if ((unsigned)s4.z < NN && (unsigned)d4.z < NN) g_esrc[atomicAdd(&g_cur[d4.z], 1)] = s4.z;
        if ((unsigned)s4.w < NN && (unsigned)d4.w < NN) g_esrc[atomicAdd(&g_cur[d4.w], 1)] = s4.w;
    } else {
#pragma unroll
        for (int q = 0; q < 4; ++q) {
            int s = edge_src(ei, e + q, 1);
            int d = edge_dst(ei, e + q, 1);
            if ((unsigned)s < NN && (unsigned)d < NN)
                g_esrc[atomicAdd(&g_cur[d], 1)] = s;
        }
    }
}

// Gather-side segment sum: 16 threads per node, one float4 column each.
// (Round-8 shape — warp-per-node variant regressed.)
// FIRST: in = g_zs, out = g_agg1 (self-loop seeded).
// else : in = g_hs2, out = d_out with fused (*dinv[dst] + b2) epilogue.
template <bool FIRST>
__global__ void k_gather(float4* __restrict__ dout, const float4* __restrict__ b2v) {
    int gt = blockIdx.x * 256 + threadIdx.x;  // exactly NN*16 threads
    int node = gt >> 4;
    int f = gt & 15;
    const float4* hs = FIRST ? (const float4*)g_zs : (const float4*)g_hs2;
    float4 acc = __ldg(hs + (size_t)node * 16 + f);  // self-loop seed
    int j = g_off[node];
    int end = j + g_cnt[node];
    // 4-way software pipeline for MLP
    for (; j + 4 <= end; j += 4) {
        int s0 = __ldg(&g_esrc[j]);
        int s1 = __ldg(&g_esrc[j + 1]);
        int s2 = __ldg(&g_esrc[j + 2]);
        int s3 = __ldg(&g_esrc[j + 3]);
        float4 v0 = __ldg(hs + (size_t)s0 * 16 + f);
        float4 v1 = __ldg(hs + (size_t)s1 * 16 + f);
        float4 v2 = __ldg(hs + (size_t)s2 * 16 + f);
        float4 v3 = __ldg(hs + (size_t)s3 * 16 + f);
        acc.x += (v0.x + v1.x) + (v2.x + v3.x);
        acc.y += (v0.y + v1.y) + (v2.y + v3.y);
        acc.z += (v0.z + v1.z) + (v2.z + v3.z);
        acc.w += (v0.w + v1.w) + (v2.w + v3.w);
    }
    for (; j < end; ++j) {
        int s0 = __ldg(&g_esrc[j]);
        float4 v0 = __ldg(hs + (size_t)s0 * 16 + f);
        acc.x += v0.x; acc.y += v0.y; acc.z += v0.z; acc.w += v0.w;
    }
    if (FIRST) {
        g_agg1[(size_t)node * 16 + f] = acc;
    } else {
        float sc = g_dinv[node];
        float4 b = __ldg(b2v + f);
        acc.x = acc.x * sc + b.x; acc.y = acc.y * sc + b.y;
        acc.z = acc.z * sc + b.z; acc.w = acc.w * sc + b.w;
        dout[(size_t)node * 16 + f] = acc;
    }
}

// Dense GEMM: ROWS rows/block, 256 threads, R=4 rows/thread, float4 zk loads.
// EPI==1: in = g_agg1 (rows scaled by dinv at load), out = relu(acc + b1) -> g_x1
// EPI==2: in = g_x1,  out = acc * dinv[row] -> g_hs2   (pre-scale by dinv[src])
template <int K, int N, int ROWS, int EPI>
__global__ void __launch_bounds__(256) k_gemm(const float* __restrict__ W,
                                              const float* __restrict__ bias) {
    constexpr int TPR = N / 8;          // threads per row-group (8 outputs each)
    constexpr int GROUPS = 256 / TPR;   // row groups per block
    constexpr int R = ROWS / GROUPS;    // rows per thread (4)
    constexpr int KT = 32;
    constexpr int RST = KT + 4;         // float stride, keeps float4 alignment

    __shared__ __align__(16) float Ws[KT * N];
    __shared__ __align__(16) float Rs[ROWS * RST];

    const float* in = (EPI == 1) ? (const float*)g_agg1 : (const float*)g_x1;

    int tid = threadIdx.x;
    int c = tid % TPR;
    int g = tid / TPR;
    int row0 = blockIdx.x * ROWS;

    float4 a0[R], a1[R];
#pragma unroll
    for (int i = 0; i < R; i++) {
        a0[i] = make_float4(0.f, 0.f, 0.f, 0.f);
        a1[i] = make_float4(0.f, 0.f, 0.f, 0.f);
    }

#pragma unroll
    for (int kt = 0; kt < K / KT; ++kt) {
        const float4* Wg = (const float4*)(W + kt * KT * N);
        float4* Ws4 = (float4*)Ws;
#pragma unroll
        for (int j = tid; j < KT * N / 4; j += 256) Ws4[j] = __ldg(Wg + j);
#pragma unroll
        for (int j = tid; j < ROWS * (KT / 4); j += 256) {
            int r = j / (KT / 4), c4 = j % (KT / 4);
            int grow = row0 + r;
            if (grow >= NN) grow = NN - 1;
            float4 v = __ldg((const float4*)(in + (size_t)grow * K + kt * KT) + c4);
            if (EPI == 1) {
                float sc = g_dinv[grow];
                v.x *= sc; v.y *= sc; v.z *= sc; v.w *= sc;
            }
            *(float4*)&Rs[r * RST + c4 * 4] = v;
        }
        __syncthreads();

        const float4* Wr = (const float4*)Ws;
#pragma unroll
        for (int kk4 = 0; kk4 < KT / 4; ++kk4) {
            float4 zk[R];
#pragma unroll
            for (int i = 0; i < R; ++i)
                zk[i] = *(const float4*)&Rs[(g * R + i) * RST + kk4 * 4];
#pragma unroll
            for (int kc = 0; kc < 4; ++kc) {
                float4 w0 = Wr[(kk4 * 4 + kc) * (N / 4) + 2 * c];
                float4 w1 = Wr[(kk4 * 4 + kc) * (N / 4) + 2 * c + 1];
#pragma unroll
                for (int i = 0; i < R; ++i) {
                    float z = (kc == 0) ? zk[i].x : (kc == 1) ? zk[i].y
                             : (kc == 2) ? zk[i].z : zk[i].w;
                    a0[i].x += z * w0.x; a0[i].y += z * w0.y;
                    a0[i].z += z * w0.z; a0[i].w += z * w0.w;
                    a1[i].x += z * w1.x; a1[i].y += z * w1.y;
                    a1[i].z += z * w1.z; a1[i].w += z * w1.w;
                }
            }
        }
        __syncthreads();
    }

#pragma unroll
    for (int i = 0; i < R; ++i) {
        int grow = row0 + g * R + i;
        if (grow >= NN) continue;
        if (EPI == 1) {
            float4 bb0 = __ldg((const float4*)bias + 2 * c);
            float4 bb1 = __ldg((const float4*)bias + 2 * c + 1);
            float4 v0, v1;
            v0.x = fmaxf(a0[i].x + bb0.x, 0.f); v0.y = fmaxf(a0[i].y + bb0.y, 0.f);
            v0.z = fmaxf(a0[i].z + bb0.z, 0.f); v0.w = fmaxf(a0[i].w + bb0.w, 0.f);
            v1.x = fmaxf(a1[i].x + bb1.x, 0.f); v1.y = fmaxf(a1[i].y + bb1.y, 0.f);
            v1.z = fmaxf(a1[i].z + bb1.z, 0.f); v1.w = fmaxf(a1[i].w + bb1.w, 0.f);
            float4* op = (float4*)g_x1 + (size_t)grow * (N / 4);
            op[2 * c] = v0;
            op[2 * c + 1] = v1;
        } else {
            float sc = g_dinv[grow];
            float4 v0, v1;
            v0.x = a0[i].x * sc; v0.y = a0[i].y * sc; v0.z = a0[i].z * sc; v0.w = a0[i].w * sc;
            v1.x = a1[i].x * sc; v1.y = a1[i].y * sc; v1.z = a1[i].z * sc; v1.w = a1[i].w * sc;
            float4* h = (float4*)g_hs2 + (size_t)grow * (N / 4);
            h[2 * c] = v0;
            h[2 * c + 1] = v1;
        }
    }
}

extern "C" void kernel_launch(void* const* d_in, const int* in_sizes, int n_in,
                              void* d_out, int out_size) {
    const float* z   = (const float*)d_in[0];
    const int* ei    = (const int*)d_in[1];   // int32 OR int64 pairs (detected)
    const float* W1  = (const float*)d_in[2];
    const float* b1  = (const float*)d_in[3];
    const float* W2  = (const float*)d_in[4];
    const float* b2  = (const float*)d_in[5];
    float* out = (float*)d_out;

    k_init<<<(NN + 255) / 256, 256>>>(ei);
    k_hist<<<(NE / 4 + 255) / 256, 256>>>(ei);
    k_scan1<<<SCAN_NB, SCAN_B>>>();
    k_scan2<<<1, 128>>>();
    k_prep<<<NN * 16 / 256, 256>>>((const float4*)z);
    k_permute<<<(NE / 4 + 255) / 256, 256>>>(ei);
    k_gather<true><<<NN * 16 / 256, 256>>>(nullptr, nullptr);
    k_gemm<64, 128, 64, 1><<<(NN + 63) / 64, 256>>>(W1, b1);
    k_gemm<128, 64, 128, 2><<<(NN + 127) / 128, 256>>>(W2, nullptr);
    k_gather<false><<<NN * 16 / 256, 256>>>((float4*)out, (const float4*)b2);
}